// round 3
// baseline (speedup 1.0000x reference)
#include <cuda_runtime.h>
#include <math.h>

#define Bn 16
#define Cn 3
#define Hn 512
#define Wn 512
#define HW (Hn * Wn)           // 262144
#define CHW (Cn * HW)          // 786432
#define NTOT (Bn * Cn * HW)    // 12582912

#define TW 64                  // owned tile width
#define TH 32                  // owned tile height
#define HTW 72                 // halo smem width: cols [w0-4, w0+67], float4-aligned
#define HTH (TH + 2)           // 34
#define VPR (HTW / 4)          // 18 float4 vectors per halo row
#define NTHREADS 256
#define PIX_PER_THREAD ((TW * TH) / NTHREADS)   // 8

#define GX (Wn / TW)           // 8
#define GY (Hn / TH)           // 16
#define BPB (GX * GY)          // 128 blocks per batch image
#define NBLK (BPB * Bn)        // 2048

// Per-block partials, written exactly once each run (no zeroing needed).
// [0]=sum(r), [1]=sum(r^2), [2]=sum(|lv|*r*mask)
__device__ double g_part[3][NBLK];

__device__ __forceinline__ int reflect(int i, int n) {
    return (i < 0) ? -i : ((i >= n) ? 2 * n - 2 - i : i);
}

// ---------------------------------------------------------------------------
__global__ __launch_bounds__(NTHREADS) void fused_kernel(
    const float* __restrict__ sr,
    const float* __restrict__ srema,
    const float* __restrict__ hr)
{
    __shared__ float rt[HTH * HTW];     // signed r_det tile (sign bit = mask)

    const int tid = threadIdx.x;
    const int w0  = blockIdx.x * TW;
    const int h0  = blockIdx.y * TH;
    const int b   = blockIdx.z;
    const long base = (long)b * CHW;

    // --- Phase 1: residual halo tile, vectorized ----------------------------
    // t indexes (row, vec): HTH rows x VPR float4 vectors.
    for (int t = tid; t < HTH * VPR; t += NTHREADS) {
        const int ty = t / VPR;
        const int v  = t - ty * VPR;
        const int gh = reflect(h0 - 1 + ty, Hn);
        const int gw0 = w0 - 4 + 4 * v;
        float4 out;
        if (gw0 >= 0 && gw0 + 3 < Wn) {
            // aligned vector path
            const long ix = base + (long)gh * Wn + gw0;
            float4 rs4 = make_float4(0.f, 0.f, 0.f, 0.f);
            float4 re4 = make_float4(0.f, 0.f, 0.f, 0.f);
#pragma unroll
            for (int c = 0; c < Cn; ++c) {
                const long o = ix + (long)c * HW;
                float4 h4  = __ldg((const float4*)(hr    + o));
                float4 s4  = __ldg((const float4*)(sr    + o));
                float4 e4  = __ldg((const float4*)(srema + o));
                rs4.x += fabsf(h4.x - s4.x); re4.x += fabsf(h4.x - e4.x);
                rs4.y += fabsf(h4.y - s4.y); re4.y += fabsf(h4.y - e4.y);
                rs4.z += fabsf(h4.z - s4.z); re4.z += fabsf(h4.z - e4.z);
                rs4.w += fabsf(h4.w - s4.w); re4.w += fabsf(h4.w - e4.w);
            }
            const float k = 1.0f / 255.0f;
            rs4.x *= k; rs4.y *= k; rs4.z *= k; rs4.w *= k;
            re4.x *= k; re4.y *= k; re4.z *= k; re4.w *= k;
            out.x = (rs4.x < re4.x) ? __int_as_float(__float_as_int(rs4.x) | 0x80000000u) : rs4.x;
            out.y = (rs4.y < re4.y) ? __int_as_float(__float_as_int(rs4.y) | 0x80000000u) : rs4.y;
            out.z = (rs4.z < re4.z) ? __int_as_float(__float_as_int(rs4.z) | 0x80000000u) : rs4.z;
            out.w = (rs4.w < re4.w) ? __int_as_float(__float_as_int(rs4.w) | 0x80000000u) : rs4.w;
        } else {
            // boundary vector of an edge block: scalar with reflect
            float vals[4];
#pragma unroll
            for (int e = 0; e < 4; ++e) {
                const int gw = reflect(gw0 + e, Wn);
                const long ix = base + (long)gh * Wn + gw;
                float rs = 0.f, re = 0.f;
#pragma unroll
                for (int c = 0; c < Cn; ++c) {
                    float h  = __ldg(hr    + ix + (long)c * HW);
                    float s  = __ldg(sr    + ix + (long)c * HW);
                    float se = __ldg(srema + ix + (long)c * HW);
                    rs += fabsf(h - s);
                    re += fabsf(h - se);
                }
                rs *= (1.0f / 255.0f);
                re *= (1.0f / 255.0f);
                vals[e] = (rs < re) ? __int_as_float(__float_as_int(rs) | 0x80000000u) : rs;
            }
            out = make_float4(vals[0], vals[1], vals[2], vals[3]);
        }
        *(float4*)(rt + ty * HTW + 4 * v) = out;   // 288B rows -> 16B aligned
    }
    __syncthreads();

    // --- Phase 2: 3x3 unbiased local variance + contribution ----------------
    float lsum = 0.f, lsq = 0.f, lS = 0.f;
#pragma unroll
    for (int k = 0; k < PIX_PER_THREAD; ++k) {
        const int p   = tid + k * NTHREADS;
        const int row = p >> 6;            // /TW
        const int col = p & 63;            // %TW
        const float* r0 = rt + row * HTW + col + 3;  // window left col = 3+col
        const float* r1 = r0 + HTW;
        const float* r2 = r1 + HTW;

        float c_s = r1[1];
        float v0 = fabsf(r0[0]), v1 = fabsf(r0[1]), v2 = fabsf(r0[2]);
        float v3 = fabsf(r1[0]), v4 = fabsf(c_s),   v5 = fabsf(r1[2]);
        float v6 = fabsf(r2[0]), v7 = fabsf(r2[1]), v8 = fabsf(r2[2]);

        float s  = v0 + v1 + v2 + v3 + v4 + v5 + v6 + v7 + v8;
        float sq = v0*v0 + v1*v1 + v2*v2 + v3*v3 + v4*v4
                 + v5*v5 + v6*v6 + v7*v7 + v8*v8;
        float lv = (sq - s * s * (1.0f / 9.0f)) * (1.0f / 8.0f);

        float contrib = signbit(c_s) ? 0.0f : fabsf(lv) * v4;
        lsum += v4;
        lsq  += v4 * v4;
        lS   += contrib;
    }

    // --- Reduction: warp shuffle, then one smem stage ------------------------
    __shared__ float wsum[8], wsq[8], wS[8];
#pragma unroll
    for (int o = 16; o > 0; o >>= 1) {
        lsum += __shfl_down_sync(0xffffffffu, lsum, o);
        lsq  += __shfl_down_sync(0xffffffffu, lsq,  o);
        lS   += __shfl_down_sync(0xffffffffu, lS,   o);
    }
    const int warp = tid >> 5;
    if ((tid & 31) == 0) { wsum[warp] = lsum; wsq[warp] = lsq; wS[warp] = lS; }
    __syncthreads();
    if (tid == 0) {
        float a = 0.f, c = 0.f, d = 0.f;
#pragma unroll
        for (int i = 0; i < 8; ++i) { a += wsum[i]; c += wsq[i]; d += wS[i]; }
        const int bid = blockIdx.x + GX * blockIdx.y + BPB * blockIdx.z;
        g_part[0][bid] = (double)a;
        g_part[1][bid] = (double)c;
        g_part[2][bid] = (double)d;
    }
}

// ---------------------------------------------------------------------------
// loss = (255 / NTOT) * sum_b  patch_var_b^0.2 * S_b
// One block of 512 threads: 32 lanes per batch, 4 partial entries per lane.
__global__ __launch_bounds__(512) void final_kernel(float* __restrict__ out) {
    const int t    = threadIdx.x;
    const int b    = t >> 5;
    const int lane = t & 31;

    double s = 0.0, sq = 0.0, S = 0.0;
#pragma unroll
    for (int j = 0; j < 4; ++j) {
        int idx = b * BPB + lane + 32 * j;
        s  += g_part[0][idx];
        sq += g_part[1][idx];
        S  += g_part[2][idx];
    }
#pragma unroll
    for (int o = 16; o > 0; o >>= 1) {
        s  += __shfl_down_sync(0xffffffffu, s,  o);
        sq += __shfl_down_sync(0xffffffffu, sq, o);
        S  += __shfl_down_sync(0xffffffffu, S,  o);
    }
    __shared__ double sres[16];
    if (lane == 0) {
        const double n = (double)HW;
        double var = (sq - s * s / n) / (n - 1.0);
        if (var < 0.0) var = 0.0;
        sres[b] = pow(var, 0.2) * S;
    }
    __syncthreads();
    if (t == 0) {
        double acc = 0.0;
#pragma unroll
        for (int i = 0; i < Bn; ++i) acc += sres[i];
        out[0] = (float)(acc * 255.0 / (double)NTOT);
    }
}

// ---------------------------------------------------------------------------
extern "C" void kernel_launch(void* const* d_in, const int* in_sizes, int n_in,
                              void* d_out, int out_size) {
    const float* sr    = (const float*)d_in[0];
    const float* srema = (const float*)d_in[1];
    const float* hr    = (const float*)d_in[2];
    float* out = (float*)d_out;

    dim3 blk(NTHREADS, 1, 1);
    dim3 grd(GX, GY, Bn);
    fused_kernel<<<grd, blk>>>(sr, srema, hr);
    final_kernel<<<1, 512>>>(out);
}

// round 4
// speedup vs baseline: 1.2683x; 1.2683x over previous
#include <cuda_runtime.h>
#include <math.h>

#define Bn 16
#define Cn 3
#define Hn 512
#define Wn 512
#define HW (Hn * Wn)           // 262144
#define CHW (Cn * HW)          // 786432
#define NTOT (Bn * Cn * HW)    // 12582912

#define TW 64                  // owned tile width
#define TH 32                  // owned tile height
#define HTW 72                 // halo smem width: cols [w0-4, w0+67], float4-aligned
#define HTH (TH + 2)           // 34
#define VPR (HTW / 4)          // 18 float4 vectors per halo row
#define NTHREADS 256
#define PIX_PER_THREAD ((TW * TH) / NTHREADS)   // 8

#define GX (Wn / TW)           // 8
#define GY (Hn / TH)           // 16
#define BPB (GX * GY)          // 128 blocks per batch image
#define NBLK (BPB * Bn)        // 2048

// Per-block float partials, each written exactly once per run (no zeroing).
// [0]=sum(r), [1]=sum(r^2), [2]=sum(|lv|*r*mask)
__device__ float g_part[3][NBLK];

__device__ __forceinline__ int reflect(int i, int n) {
    return (i < 0) ? -i : ((i >= n) ? 2 * n - 2 - i : i);
}

// ---------------------------------------------------------------------------
__global__ __launch_bounds__(NTHREADS) void fused_kernel(
    const float* __restrict__ sr,
    const float* __restrict__ srema,
    const float* __restrict__ hr)
{
    __shared__ float rt[HTH * HTW];     // signed r_det tile (sign bit = mask)

    const int tid = threadIdx.x;
    const int w0  = blockIdx.x * TW;
    const int h0  = blockIdx.y * TH;
    const int b   = blockIdx.z;
    const long base = (long)b * CHW;

    // --- Phase 1: residual halo tile, float4 vectorized ----------------------
    for (int t = tid; t < HTH * VPR; t += NTHREADS) {
        const int ty = t / VPR;
        const int v  = t - ty * VPR;
        const int gh = reflect(h0 - 1 + ty, Hn);
        const int gw0 = w0 - 4 + 4 * v;
        float4 out;
        if (gw0 >= 0 && gw0 + 3 < Wn) {
            const long ix = base + (long)gh * Wn + gw0;
            float4 rs4 = make_float4(0.f, 0.f, 0.f, 0.f);
            float4 re4 = make_float4(0.f, 0.f, 0.f, 0.f);
#pragma unroll
            for (int c = 0; c < Cn; ++c) {
                const long o = ix + (long)c * HW;
                float4 h4  = __ldg((const float4*)(hr    + o));
                float4 s4  = __ldg((const float4*)(sr    + o));
                float4 e4  = __ldg((const float4*)(srema + o));
                rs4.x += fabsf(h4.x - s4.x); re4.x += fabsf(h4.x - e4.x);
                rs4.y += fabsf(h4.y - s4.y); re4.y += fabsf(h4.y - e4.y);
                rs4.z += fabsf(h4.z - s4.z); re4.z += fabsf(h4.z - e4.z);
                rs4.w += fabsf(h4.w - s4.w); re4.w += fabsf(h4.w - e4.w);
            }
            const float k = 1.0f / 255.0f;
            rs4.x *= k; rs4.y *= k; rs4.z *= k; rs4.w *= k;
            re4.x *= k; re4.y *= k; re4.z *= k; re4.w *= k;
            out.x = (rs4.x < re4.x) ? __int_as_float(__float_as_int(rs4.x) | 0x80000000u) : rs4.x;
            out.y = (rs4.y < re4.y) ? __int_as_float(__float_as_int(rs4.y) | 0x80000000u) : rs4.y;
            out.z = (rs4.z < re4.z) ? __int_as_float(__float_as_int(rs4.z) | 0x80000000u) : rs4.z;
            out.w = (rs4.w < re4.w) ? __int_as_float(__float_as_int(rs4.w) | 0x80000000u) : rs4.w;
        } else {
            float vals[4];
#pragma unroll
            for (int e = 0; e < 4; ++e) {
                const int gw = reflect(gw0 + e, Wn);
                const long ix = base + (long)gh * Wn + gw;
                float rs = 0.f, re = 0.f;
#pragma unroll
                for (int c = 0; c < Cn; ++c) {
                    float h  = __ldg(hr    + ix + (long)c * HW);
                    float s  = __ldg(sr    + ix + (long)c * HW);
                    float se = __ldg(srema + ix + (long)c * HW);
                    rs += fabsf(h - s);
                    re += fabsf(h - se);
                }
                rs *= (1.0f / 255.0f);
                re *= (1.0f / 255.0f);
                vals[e] = (rs < re) ? __int_as_float(__float_as_int(rs) | 0x80000000u) : rs;
            }
            out = make_float4(vals[0], vals[1], vals[2], vals[3]);
        }
        *(float4*)(rt + ty * HTW + 4 * v) = out;
    }
    __syncthreads();

    // --- Phase 2: 3x3 unbiased local variance + contribution ----------------
    float lsum = 0.f, lsq = 0.f, lS = 0.f;
#pragma unroll
    for (int k = 0; k < PIX_PER_THREAD; ++k) {
        const int p   = tid + k * NTHREADS;
        const int row = p >> 6;
        const int col = p & 63;
        const float* r0 = rt + row * HTW + col + 3;
        const float* r1 = r0 + HTW;
        const float* r2 = r1 + HTW;

        float c_s = r1[1];
        float v0 = fabsf(r0[0]), v1 = fabsf(r0[1]), v2 = fabsf(r0[2]);
        float v3 = fabsf(r1[0]), v4 = fabsf(c_s),   v5 = fabsf(r1[2]);
        float v6 = fabsf(r2[0]), v7 = fabsf(r2[1]), v8 = fabsf(r2[2]);

        float s  = v0 + v1 + v2 + v3 + v4 + v5 + v6 + v7 + v8;
        float sq = v0*v0 + v1*v1 + v2*v2 + v3*v3 + v4*v4
                 + v5*v5 + v6*v6 + v7*v7 + v8*v8;
        float lv = (sq - s * s * (1.0f / 9.0f)) * (1.0f / 8.0f);

        float contrib = signbit(c_s) ? 0.0f : fabsf(lv) * v4;
        lsum += v4;
        lsq  += v4 * v4;
        lS   += contrib;
    }

    // --- Reduction: warp shuffle, then one smem stage ------------------------
    __shared__ float wsum[8], wsq[8], wS[8];
#pragma unroll
    for (int o = 16; o > 0; o >>= 1) {
        lsum += __shfl_down_sync(0xffffffffu, lsum, o);
        lsq  += __shfl_down_sync(0xffffffffu, lsq,  o);
        lS   += __shfl_down_sync(0xffffffffu, lS,   o);
    }
    const int warp = tid >> 5;
    if ((tid & 31) == 0) { wsum[warp] = lsum; wsq[warp] = lsq; wS[warp] = lS; }
    __syncthreads();
    if (tid == 0) {
        float a = 0.f, c = 0.f, d = 0.f;
#pragma unroll
        for (int i = 0; i < 8; ++i) { a += wsum[i]; c += wsq[i]; d += wS[i]; }
        const int bid = blockIdx.x + GX * blockIdx.y + BPB * blockIdx.z;
        g_part[0][bid] = a;
        g_part[1][bid] = c;
        g_part[2][bid] = d;
    }
}

// ---------------------------------------------------------------------------
// loss = (255 / NTOT) * sum_b  patch_var_b^0.2 * S_b
// 512 threads: one warp per batch. Lane loads one float4 per partial array
// (coalesced), double accumulation, fp32 exp2/log2 for the ^0.2.
__global__ __launch_bounds__(512) void final_kernel(float* __restrict__ out) {
    const int t    = threadIdx.x;
    const int b    = t >> 5;
    const int lane = t & 31;

    const int idx = b * BPB + lane * 4;   // 128 partials per batch, float4 per lane
    float4 p0 = *(const float4*)&g_part[0][idx];
    float4 p1 = *(const float4*)&g_part[1][idx];
    float4 p2 = *(const float4*)&g_part[2][idx];

    double s  = (double)p0.x + p0.y + p0.z + p0.w;
    double sq = (double)p1.x + p1.y + p1.z + p1.w;
    double S  = (double)p2.x + p2.y + p2.z + p2.w;

#pragma unroll
    for (int o = 16; o > 0; o >>= 1) {
        s  += __shfl_down_sync(0xffffffffu, s,  o);
        sq += __shfl_down_sync(0xffffffffu, sq, o);
        S  += __shfl_down_sync(0xffffffffu, S,  o);
    }

    __shared__ float sres[Bn];
    if (lane == 0) {
        const double n = (double)HW;
        double var = (sq - s * s / n) / (n - 1.0);
        float w = (var > 0.0) ? exp2f(0.2f * log2f((float)var)) : 0.0f;
        sres[b] = w * (float)S;
    }
    __syncthreads();
    if (t == 0) {
        float acc = 0.f;
#pragma unroll
        for (int i = 0; i < Bn; ++i) acc += sres[i];
        out[0] = acc * (255.0f / (float)NTOT);
    }
}

// ---------------------------------------------------------------------------
extern "C" void kernel_launch(void* const* d_in, const int* in_sizes, int n_in,
                              void* d_out, int out_size) {
    const float* sr    = (const float*)d_in[0];
    const float* srema = (const float*)d_in[1];
    const float* hr    = (const float*)d_in[2];
    float* out = (float*)d_out;

    dim3 blk(NTHREADS, 1, 1);
    dim3 grd(GX, GY, Bn);
    fused_kernel<<<grd, blk>>>(sr, srema, hr);
    final_kernel<<<1, 512>>>(out);
}

// round 5
// speedup vs baseline: 1.3405x; 1.0569x over previous
#include <cuda_runtime.h>
#include <math.h>

#define Bn 16
#define Cn 3
#define Hn 512
#define Wn 512
#define HW (Hn * Wn)           // 262144
#define CHW (Cn * HW)          // 786432
#define NTOT (Bn * Cn * HW)    // 12582912

#define TW 128                 // owned tile width
#define TH 32                  // owned tile height
#define HTW 136                // halo smem width: cols [w0-4, w0+131], float4-aligned
#define HTH (TH + 2)           // 34
#define VPR (HTW / 4)          // 34 float4 vectors per halo row
#define NTHREADS 512
#define PIX_PER_THREAD ((TW * TH) / NTHREADS)   // 8

#define GX (Wn / TW)           // 4
#define GY (Hn / TH)           // 16
#define BPB (GX * GY)          // 64 blocks per batch image
#define NBLK (BPB * Bn)        // 1024

// Per-block float partials, each written exactly once per run (no zeroing).
// [0]=sum(r), [1]=sum(r^2), [2]=sum(|lv|*r*mask)
__device__ float g_part[3][NBLK];
__device__ unsigned int g_count;   // zero-initialized; last block resets to 0

__device__ __forceinline__ int reflect(int i, int n) {
    return (i < 0) ? -i : ((i >= n) ? 2 * n - 2 - i : i);
}

// ---------------------------------------------------------------------------
__global__ __launch_bounds__(NTHREADS) void fused_kernel(
    const float* __restrict__ sr,
    const float* __restrict__ srema,
    const float* __restrict__ hr,
    float* __restrict__ out)
{
    __shared__ float rt[HTH * HTW];     // signed r_det tile (sign bit = mask)

    const int tid = threadIdx.x;
    const int w0  = blockIdx.x * TW;
    const int h0  = blockIdx.y * TH;
    const int b   = blockIdx.z;
    const long base = (long)b * CHW;

    // --- Phase 1: residual halo tile, float4 vectorized ----------------------
    for (int t = tid; t < HTH * VPR; t += NTHREADS) {
        const int ty = t / VPR;
        const int v  = t - ty * VPR;
        const int gh = reflect(h0 - 1 + ty, Hn);
        const int gw0 = w0 - 4 + 4 * v;
        float4 o4;
        if (gw0 >= 0 && gw0 + 3 < Wn) {
            const long ix = base + (long)gh * Wn + gw0;
            float4 rs4 = make_float4(0.f, 0.f, 0.f, 0.f);
            float4 re4 = make_float4(0.f, 0.f, 0.f, 0.f);
#pragma unroll
            for (int c = 0; c < Cn; ++c) {
                const long o = ix + (long)c * HW;
                float4 h4  = __ldg((const float4*)(hr    + o));
                float4 s4  = __ldg((const float4*)(sr    + o));
                float4 e4  = __ldg((const float4*)(srema + o));
                rs4.x += fabsf(h4.x - s4.x); re4.x += fabsf(h4.x - e4.x);
                rs4.y += fabsf(h4.y - s4.y); re4.y += fabsf(h4.y - e4.y);
                rs4.z += fabsf(h4.z - s4.z); re4.z += fabsf(h4.z - e4.z);
                rs4.w += fabsf(h4.w - s4.w); re4.w += fabsf(h4.w - e4.w);
            }
            const float k = 1.0f / 255.0f;
            rs4.x *= k; rs4.y *= k; rs4.z *= k; rs4.w *= k;
            re4.x *= k; re4.y *= k; re4.z *= k; re4.w *= k;
            o4.x = (rs4.x < re4.x) ? __int_as_float(__float_as_int(rs4.x) | 0x80000000u) : rs4.x;
            o4.y = (rs4.y < re4.y) ? __int_as_float(__float_as_int(rs4.y) | 0x80000000u) : rs4.y;
            o4.z = (rs4.z < re4.z) ? __int_as_float(__float_as_int(rs4.z) | 0x80000000u) : rs4.z;
            o4.w = (rs4.w < re4.w) ? __int_as_float(__float_as_int(rs4.w) | 0x80000000u) : rs4.w;
        } else {
            float vals[4];
#pragma unroll
            for (int e = 0; e < 4; ++e) {
                const int gw = reflect(gw0 + e, Wn);
                const long ix = base + (long)gh * Wn + gw;
                float rs = 0.f, re = 0.f;
#pragma unroll
                for (int c = 0; c < Cn; ++c) {
                    float h  = __ldg(hr    + ix + (long)c * HW);
                    float s  = __ldg(sr    + ix + (long)c * HW);
                    float se = __ldg(srema + ix + (long)c * HW);
                    rs += fabsf(h - s);
                    re += fabsf(h - se);
                }
                rs *= (1.0f / 255.0f);
                re *= (1.0f / 255.0f);
                vals[e] = (rs < re) ? __int_as_float(__float_as_int(rs) | 0x80000000u) : rs;
            }
            o4 = make_float4(vals[0], vals[1], vals[2], vals[3]);
        }
        *(float4*)(rt + ty * HTW + 4 * v) = o4;
    }
    __syncthreads();

    // --- Phase 2: 3x3 unbiased local variance + contribution ----------------
    float lsum = 0.f, lsq = 0.f, lS = 0.f;
#pragma unroll
    for (int k = 0; k < PIX_PER_THREAD; ++k) {
        const int p   = tid + k * NTHREADS;
        const int row = p >> 7;            // /TW
        const int col = p & 127;           // %TW
        const float* r0 = rt + row * HTW + col + 3;  // owned col c -> halo c+4, window left c+3
        const float* r1 = r0 + HTW;
        const float* r2 = r1 + HTW;

        float c_s = r1[1];
        float v0 = fabsf(r0[0]), v1 = fabsf(r0[1]), v2 = fabsf(r0[2]);
        float v3 = fabsf(r1[0]), v4 = fabsf(c_s),   v5 = fabsf(r1[2]);
        float v6 = fabsf(r2[0]), v7 = fabsf(r2[1]), v8 = fabsf(r2[2]);

        float s  = v0 + v1 + v2 + v3 + v4 + v5 + v6 + v7 + v8;
        float sq = v0*v0 + v1*v1 + v2*v2 + v3*v3 + v4*v4
                 + v5*v5 + v6*v6 + v7*v7 + v8*v8;
        float lv = (sq - s * s * (1.0f / 9.0f)) * (1.0f / 8.0f);

        float contrib = signbit(c_s) ? 0.0f : fabsf(lv) * v4;
        lsum += v4;
        lsq  += v4 * v4;
        lS   += contrib;
    }

    // --- Block reduction -----------------------------------------------------
    __shared__ float wsum[16], wsq[16], wS[16];
#pragma unroll
    for (int o = 16; o > 0; o >>= 1) {
        lsum += __shfl_down_sync(0xffffffffu, lsum, o);
        lsq  += __shfl_down_sync(0xffffffffu, lsq,  o);
        lS   += __shfl_down_sync(0xffffffffu, lS,   o);
    }
    const int warp = tid >> 5;
    if ((tid & 31) == 0) { wsum[warp] = lsum; wsq[warp] = lsq; wS[warp] = lS; }
    __syncthreads();

    __shared__ bool isLast;
    if (tid == 0) {
        float a = 0.f, c = 0.f, d = 0.f;
#pragma unroll
        for (int i = 0; i < 16; ++i) { a += wsum[i]; c += wsq[i]; d += wS[i]; }
        const int bid = blockIdx.x + GX * blockIdx.y + BPB * blockIdx.z;
        g_part[0][bid] = a;
        g_part[1][bid] = c;
        g_part[2][bid] = d;
        __threadfence();
        unsigned prev = atomicAdd(&g_count, 1u);
        isLast = (prev == NBLK - 1);
    }
    __syncthreads();

    // --- Last block: per-batch patch weight + final loss ---------------------
    if (isLast) {
        if (tid == 0) g_count = 0;   // reset for next (graph-replayed) launch
        // 16 warps, warp bb handles batch bb (BPB=64 partials: lane and lane+32).
        const int bb   = tid >> 5;
        const int lane = tid & 31;
        const int pb   = bb * BPB;
        // __ldcg: L2 read, bypass (non-coherent) L1
        float s  = __ldcg(&g_part[0][pb + lane]) + __ldcg(&g_part[0][pb + lane + 32]);
        float sq = __ldcg(&g_part[1][pb + lane]) + __ldcg(&g_part[1][pb + lane + 32]);
        float S  = __ldcg(&g_part[2][pb + lane]) + __ldcg(&g_part[2][pb + lane + 32]);
#pragma unroll
        for (int o = 16; o > 0; o >>= 1) {
            s  += __shfl_down_sync(0xffffffffu, s,  o);
            sq += __shfl_down_sync(0xffffffffu, sq, o);
            S  += __shfl_down_sync(0xffffffffu, S,  o);
        }
        __shared__ float sres[Bn];
        if (lane == 0) {
            const float n = (float)HW;
            float var = (sq - s * s / n) / (n - 1.0f);
            float w = (var > 0.0f) ? exp2f(0.2f * log2f(var)) : 0.0f;
            sres[bb] = w * S;
        }
        __syncthreads();
        if (tid == 0) {
            float acc = 0.f;
#pragma unroll
            for (int i = 0; i < Bn; ++i) acc += sres[i];
            out[0] = acc * (255.0f / (float)NTOT);
        }
    }
}

// ---------------------------------------------------------------------------
extern "C" void kernel_launch(void* const* d_in, const int* in_sizes, int n_in,
                              void* d_out, int out_size) {
    const float* sr    = (const float*)d_in[0];
    const float* srema = (const float*)d_in[1];
    const float* hr    = (const float*)d_in[2];
    float* out = (float*)d_out;

    dim3 blk(NTHREADS, 1, 1);
    dim3 grd(GX, GY, Bn);
    fused_kernel<<<grd, blk>>>(sr, srema, hr, out);
}

// round 6
// speedup vs baseline: 1.4637x; 1.0919x over previous
#include <cuda_runtime.h>
#include <math.h>

#define Bn 16
#define Cn 3
#define Hn 512
#define Wn 512
#define HW (Hn * Wn)           // 262144
#define CHW (Cn * HW)          // 786432
#define NTOT (Bn * Cn * HW)    // 12582912

#define TW 64                  // owned tile width
#define TH 32                  // owned tile height
#define HTW 72                 // halo smem width: cols [w0-4, w0+67], float4-aligned
#define HTH (TH + 2)           // 34
#define VPR (HTW / 4)          // 18 float4 vectors per halo row
#define NTHREADS 256
#define PIX_PER_THREAD ((TW * TH) / NTHREADS)   // 8

#define GX (Wn / TW)           // 8
#define GY (Hn / TH)           // 16
#define BPB (GX * GY)          // 128 blocks per batch image
#define NBLK (BPB * Bn)        // 2048

// Per-block float partials, each written exactly once per run (no zeroing).
// [0]=sum(r), [1]=sum(r^2), [2]=sum(|lv|*r*mask)
__device__ float g_part[3][NBLK];
__device__ unsigned int g_count;   // zero-initialized; last block resets to 0

__device__ __forceinline__ int reflect(int i, int n) {
    return (i < 0) ? -i : ((i >= n) ? 2 * n - 2 - i : i);
}

// ---------------------------------------------------------------------------
__global__ __launch_bounds__(NTHREADS) void fused_kernel(
    const float* __restrict__ sr,
    const float* __restrict__ srema,
    const float* __restrict__ hr,
    float* __restrict__ out)
{
    __shared__ float rt[HTH * HTW];     // signed r_det tile (sign bit = mask)

    const int tid = threadIdx.x;
    const int w0  = blockIdx.x * TW;
    const int h0  = blockIdx.y * TH;
    const int b   = blockIdx.z;
    const int base = b * CHW;           // < 12.6M, fits int

    // --- Phase 1: residual halo tile, float4 vectorized ----------------------
    // 34 rows x 18 vectors = 612 items, 256 threads -> <=3 iterations.
    for (int t = tid; t < HTH * VPR; t += NTHREADS) {
        const int ty = t / VPR;
        const int v  = t - ty * VPR;
        const int gh = reflect(h0 - 1 + ty, Hn);
        const int gw0 = w0 - 4 + 4 * v;
        float4 o4;
        if (gw0 >= 0 && gw0 + 3 < Wn) {
            const int ix = base + gh * Wn + gw0;
            float4 rs4 = make_float4(0.f, 0.f, 0.f, 0.f);
            float4 re4 = make_float4(0.f, 0.f, 0.f, 0.f);
#pragma unroll
            for (int c = 0; c < Cn; ++c) {
                const int o = ix + c * HW;
                float4 h4  = __ldg((const float4*)(hr    + o));
                float4 s4  = __ldg((const float4*)(sr    + o));
                float4 e4  = __ldg((const float4*)(srema + o));
                rs4.x += fabsf(h4.x - s4.x); re4.x += fabsf(h4.x - e4.x);
                rs4.y += fabsf(h4.y - s4.y); re4.y += fabsf(h4.y - e4.y);
                rs4.z += fabsf(h4.z - s4.z); re4.z += fabsf(h4.z - e4.z);
                rs4.w += fabsf(h4.w - s4.w); re4.w += fabsf(h4.w - e4.w);
            }
            const float k = 1.0f / 255.0f;
            rs4.x *= k; rs4.y *= k; rs4.z *= k; rs4.w *= k;
            re4.x *= k; re4.y *= k; re4.z *= k; re4.w *= k;
            o4.x = (rs4.x < re4.x) ? __int_as_float(__float_as_int(rs4.x) | 0x80000000u) : rs4.x;
            o4.y = (rs4.y < re4.y) ? __int_as_float(__float_as_int(rs4.y) | 0x80000000u) : rs4.y;
            o4.z = (rs4.z < re4.z) ? __int_as_float(__float_as_int(rs4.z) | 0x80000000u) : rs4.z;
            o4.w = (rs4.w < re4.w) ? __int_as_float(__float_as_int(rs4.w) | 0x80000000u) : rs4.w;
        } else {
            float vals[4];
#pragma unroll
            for (int e = 0; e < 4; ++e) {
                const int gw = reflect(gw0 + e, Wn);
                const int ix = base + gh * Wn + gw;
                float rs = 0.f, re = 0.f;
#pragma unroll
                for (int c = 0; c < Cn; ++c) {
                    float h  = __ldg(hr    + ix + c * HW);
                    float s  = __ldg(sr    + ix + c * HW);
                    float se = __ldg(srema + ix + c * HW);
                    rs += fabsf(h - s);
                    re += fabsf(h - se);
                }
                rs *= (1.0f / 255.0f);
                re *= (1.0f / 255.0f);
                vals[e] = (rs < re) ? __int_as_float(__float_as_int(rs) | 0x80000000u) : rs;
            }
            o4 = make_float4(vals[0], vals[1], vals[2], vals[3]);
        }
        *(float4*)(rt + ty * HTW + 4 * v) = o4;
    }
    __syncthreads();

    // --- Phase 2: 3x3 unbiased local variance + contribution ----------------
    float lsum = 0.f, lsq = 0.f, lS = 0.f;
#pragma unroll
    for (int k = 0; k < PIX_PER_THREAD; ++k) {
        const int p   = tid + k * NTHREADS;
        const int row = p >> 6;            // /TW
        const int col = p & 63;            // %TW
        const float* r0 = rt + row * HTW + col + 3;  // owned col c -> halo c+4, window left c+3
        const float* r1 = r0 + HTW;
        const float* r2 = r1 + HTW;

        float c_s = r1[1];
        float v0 = fabsf(r0[0]), v1 = fabsf(r0[1]), v2 = fabsf(r0[2]);
        float v3 = fabsf(r1[0]), v4 = fabsf(c_s),   v5 = fabsf(r1[2]);
        float v6 = fabsf(r2[0]), v7 = fabsf(r2[1]), v8 = fabsf(r2[2]);

        float s  = v0 + v1 + v2 + v3 + v4 + v5 + v6 + v7 + v8;
        float sq = v0*v0 + v1*v1 + v2*v2 + v3*v3 + v4*v4
                 + v5*v5 + v6*v6 + v7*v7 + v8*v8;
        float lv = (sq - s * s * (1.0f / 9.0f)) * (1.0f / 8.0f);

        float contrib = signbit(c_s) ? 0.0f : fabsf(lv) * v4;
        lsum += v4;
        lsq  += v4 * v4;
        lS   += contrib;
    }

    // --- Block reduction -----------------------------------------------------
    __shared__ float wsum[8], wsq[8], wS[8];
#pragma unroll
    for (int o = 16; o > 0; o >>= 1) {
        lsum += __shfl_down_sync(0xffffffffu, lsum, o);
        lsq  += __shfl_down_sync(0xffffffffu, lsq,  o);
        lS   += __shfl_down_sync(0xffffffffu, lS,   o);
    }
    const int warp = tid >> 5;
    if ((tid & 31) == 0) { wsum[warp] = lsum; wsq[warp] = lsq; wS[warp] = lS; }
    __syncthreads();

    __shared__ bool isLast;
    if (tid == 0) {
        float a = 0.f, c = 0.f, d = 0.f;
#pragma unroll
        for (int i = 0; i < 8; ++i) { a += wsum[i]; c += wsq[i]; d += wS[i]; }
        const int bid = blockIdx.x + GX * blockIdx.y + BPB * blockIdx.z;
        g_part[0][bid] = a;
        g_part[1][bid] = c;
        g_part[2][bid] = d;
        __threadfence();
        unsigned prev = atomicAdd(&g_count, 1u);
        isLast = (prev == NBLK - 1);
    }
    __syncthreads();

    // --- Last block: per-batch patch weight + final loss ---------------------
    if (isLast) {
        if (tid == 0) g_count = 0;   // reset for next graph replay
        __shared__ float sres[Bn];
        const int warp2 = tid >> 5;
        const int lane  = tid & 31;
        // 8 warps, each handles 2 batches; BPB=128 partials per batch = 4/lane.
#pragma unroll
        for (int j = 0; j < 2; ++j) {
            const int bb = warp2 * 2 + j;
            const int idx = bb * BPB + lane * 4;
            // L2 reads (bypass non-coherent L1)
            float s = 0.f, sq = 0.f, S = 0.f;
#pragma unroll
            for (int e = 0; e < 4; ++e) {
                s  += __ldcg(&g_part[0][idx + e]);
                sq += __ldcg(&g_part[1][idx + e]);
                S  += __ldcg(&g_part[2][idx + e]);
            }
#pragma unroll
            for (int o = 16; o > 0; o >>= 1) {
                s  += __shfl_down_sync(0xffffffffu, s,  o);
                sq += __shfl_down_sync(0xffffffffu, sq, o);
                S  += __shfl_down_sync(0xffffffffu, S,  o);
            }
            if (lane == 0) {
                const float n = (float)HW;
                float var = (sq - s * s / n) / (n - 1.0f);
                float w = (var > 0.0f) ? exp2f(0.2f * log2f(var)) : 0.0f;
                sres[bb] = w * S;
            }
        }
        __syncthreads();
        if (tid == 0) {
            float acc = 0.f;
#pragma unroll
            for (int i = 0; i < Bn; ++i) acc += sres[i];
            out[0] = acc * (255.0f / (float)NTOT);
        }
    }
}

// ---------------------------------------------------------------------------
extern "C" void kernel_launch(void* const* d_in, const int* in_sizes, int n_in,
                              void* d_out, int out_size) {
    const float* sr    = (const float*)d_in[0];
    const float* srema = (const float*)d_in[1];
    const float* hr    = (const float*)d_in[2];
    float* out = (float*)d_out;

    dim3 blk(NTHREADS, 1, 1);
    dim3 grd(GX, GY, Bn);
    fused_kernel<<<grd, blk>>>(sr, srema, hr, out);
}